// round 4
// baseline (speedup 1.0000x reference)
#include <cuda_runtime.h>
#include <math.h>
#include <stdint.h>

// Problem constants (shapes fixed by the dataset)
#define BROWS 16384
#define DDIM  2048
#define EEXP  64
#define NCOL  128   // gate logits [0,64) | noise logits [64,128)

// GEMM tiling
#define BM 128
#define BN 128
#define BK 16
#define TM 8
#define TN 8
#define LDTA 264          // A-dup smem row stride in floats (2*128 + 8 pad), 16B-aligned
#define LDTB 132          // B smem row stride in floats (128 + 4 pad), 16B-aligned
#define NTILES (DDIM / BK)

// dynamic smem: As2[2][BK][LDTA] then Bs[2][BK][LDTB]
#define AS2_FLOATS (2 * BK * LDTA)
#define BS_FLOATS  (2 * BK * LDTB)
#define SMEM_BYTES ((AS2_FLOATS + BS_FLOATS) * 4)

// Scratch for logits: 16384 * 128 * 4 = 8 MB (static __device__, allowed)
__device__ float g_logits[(size_t)BROWS * NCOL];

// ---- packed fp32x2 helpers (PTX f32x2 ops: plain sm_100+ feature, legal on compute_103) ----
__device__ __forceinline__ double dup_f32x2(float v) {
    double d;
    asm("mov.b64 %0, {%1, %1};" : "=d"(d) : "f"(v));
    return d;
}
#define FMA2(acc, a, b) \
    asm("fma.rn.f32x2 %0, %1, %2, %0;" : "+d"(acc) : "d"(a), "d"(b))

__device__ __forceinline__ float lo_f32(double d) {
    float lo, hi;
    asm("mov.b64 {%0, %1}, %2;" : "=f"(lo), "=f"(hi) : "d"(d));
    return lo;
}
__device__ __forceinline__ float hi_f32(double d) {
    float lo, hi;
    asm("mov.b64 {%0, %1}, %2;" : "=f"(lo), "=f"(hi) : "d"(d));
    return hi;
}

__global__ __launch_bounds__(256, 1)
void sg_gemm(const float* __restrict__ x,
             const float* __restrict__ gw,
             const float* __restrict__ nw)
{
    extern __shared__ float smem[];
    float* As2 = smem;                 // [2][BK][LDTA], element-duplicated: [k][2m]=[k][2m+1]=A[m][k]
    float* Bs  = smem + AS2_FLOATS;    // [2][BK][LDTB], transposed: [k][n]

    const int tid = threadIdx.x;
    const int m0  = blockIdx.x * BM;
    const int tx  = tid & 15;   // 0..15 -> output col group (TN cols)
    const int ty  = tid >> 4;   // 0..15 -> output row group (TM rows)

    // Global load mapping: each thread loads 2 float4 from A and 2 from W per tile
    const int lrow = tid >> 2;        // 0..63
    const int lcol = (tid & 3) * 4;   // 0,4,8,12 (k within tile)

    const float* aptr0 = x  + (size_t)(m0 + lrow)      * DDIM + lcol;
    const float* aptr1 = x  + (size_t)(m0 + lrow + 64) * DDIM + lcol;
    // combined weight matrix row j: j<64 -> gate[j], j>=64 -> noise[j-64]
    const float* wptr0 = gw + (size_t)lrow * DDIM + lcol;   // cols 0..63
    const float* wptr1 = nw + (size_t)lrow * DDIM + lcol;   // cols 64..127

    // 32 packed f32x2 accumulators (8 rows x 4 col-pairs)
    double acc2[TM][TN / 2];
#pragma unroll
    for (int i = 0; i < TM; ++i)
#pragma unroll
        for (int j = 0; j < TN / 2; ++j) acc2[i][j] = 0.0;  // bit pattern {0.f,0.f}

    // preload tile 0 into registers
    float4 ra0 = *(const float4*)(aptr0);
    float4 ra1 = *(const float4*)(aptr1);
    float4 rw0 = *(const float4*)(wptr0);
    float4 rw1 = *(const float4*)(wptr1);

    // stage tile 0 into buffer 0
    {
        float* A = As2;               // buf 0
        float* B = Bs;
        // A: duplicated pairs at [k][2m],[2m+1]
        *(double*)&A[(lcol + 0) * LDTA + 2 * lrow]        = dup_f32x2(ra0.x);
        *(double*)&A[(lcol + 1) * LDTA + 2 * lrow]        = dup_f32x2(ra0.y);
        *(double*)&A[(lcol + 2) * LDTA + 2 * lrow]        = dup_f32x2(ra0.z);
        *(double*)&A[(lcol + 3) * LDTA + 2 * lrow]        = dup_f32x2(ra0.w);
        *(double*)&A[(lcol + 0) * LDTA + 2 * (lrow + 64)] = dup_f32x2(ra1.x);
        *(double*)&A[(lcol + 1) * LDTA + 2 * (lrow + 64)] = dup_f32x2(ra1.y);
        *(double*)&A[(lcol + 2) * LDTA + 2 * (lrow + 64)] = dup_f32x2(ra1.z);
        *(double*)&A[(lcol + 3) * LDTA + 2 * (lrow + 64)] = dup_f32x2(ra1.w);
        B[(lcol + 0) * LDTB + lrow]      = rw0.x;
        B[(lcol + 1) * LDTB + lrow]      = rw0.y;
        B[(lcol + 2) * LDTB + lrow]      = rw0.z;
        B[(lcol + 3) * LDTB + lrow]      = rw0.w;
        B[(lcol + 0) * LDTB + lrow + 64] = rw1.x;
        B[(lcol + 1) * LDTB + lrow + 64] = rw1.y;
        B[(lcol + 2) * LDTB + lrow + 64] = rw1.z;
        B[(lcol + 3) * LDTB + lrow + 64] = rw1.w;
    }
    __syncthreads();

    int cur = 0;
    for (int t = 0; t < NTILES; ++t) {
        const bool have_next = (t + 1 < NTILES);
        if (have_next) {
            const int off = (t + 1) * BK;
            ra0 = *(const float4*)(aptr0 + off);
            ra1 = *(const float4*)(aptr1 + off);
            rw0 = *(const float4*)(wptr0 + off);
            rw1 = *(const float4*)(wptr1 + off);
        }

        const float* Abuf = As2 + cur * (BK * LDTA);
        const float* Bbuf = Bs  + cur * (BK * LDTB);

#pragma unroll
        for (int k = 0; k < BK; ++k) {
            const float* Ak = Abuf + k * LDTA + 2 * (ty * TM);
            const float* Bk = Bbuf + k * LDTB + tx * TN;
            // A dup-pairs: 4 x LDS.128, each double2 = {v_i,v_i},{v_{i+1},v_{i+1}}
            double2 a0 = *(const double2*)(Ak + 0);
            double2 a1 = *(const double2*)(Ak + 4);
            double2 a2 = *(const double2*)(Ak + 8);
            double2 a3 = *(const double2*)(Ak + 12);
            // B pairs: 2 x LDS.128, double2 = {b0,b1},{b2,b3}
            double2 b0 = *(const double2*)(Bk + 0);
            double2 b1 = *(const double2*)(Bk + 4);

            double av[TM] = {a0.x, a0.y, a1.x, a1.y, a2.x, a2.y, a3.x, a3.y};
            double bv[TN / 2] = {b0.x, b0.y, b1.x, b1.y};
#pragma unroll
            for (int i = 0; i < TM; ++i)
#pragma unroll
                for (int j = 0; j < TN / 2; ++j)
                    FMA2(acc2[i][j], av[i], bv[j]);
        }

        if (have_next) {
            const int nxt = cur ^ 1;
            float* A = As2 + nxt * (BK * LDTA);
            float* B = Bs  + nxt * (BK * LDTB);
            *(double*)&A[(lcol + 0) * LDTA + 2 * lrow]        = dup_f32x2(ra0.x);
            *(double*)&A[(lcol + 1) * LDTA + 2 * lrow]        = dup_f32x2(ra0.y);
            *(double*)&A[(lcol + 2) * LDTA + 2 * lrow]        = dup_f32x2(ra0.z);
            *(double*)&A[(lcol + 3) * LDTA + 2 * lrow]        = dup_f32x2(ra0.w);
            *(double*)&A[(lcol + 0) * LDTA + 2 * (lrow + 64)] = dup_f32x2(ra1.x);
            *(double*)&A[(lcol + 1) * LDTA + 2 * (lrow + 64)] = dup_f32x2(ra1.y);
            *(double*)&A[(lcol + 2) * LDTA + 2 * (lrow + 64)] = dup_f32x2(ra1.z);
            *(double*)&A[(lcol + 3) * LDTA + 2 * (lrow + 64)] = dup_f32x2(ra1.w);
            B[(lcol + 0) * LDTB + lrow]      = rw0.x;
            B[(lcol + 1) * LDTB + lrow]      = rw0.y;
            B[(lcol + 2) * LDTB + lrow]      = rw0.z;
            B[(lcol + 3) * LDTB + lrow]      = rw0.w;
            B[(lcol + 0) * LDTB + lrow + 64] = rw1.x;
            B[(lcol + 1) * LDTB + lrow + 64] = rw1.y;
            B[(lcol + 2) * LDTB + lrow + 64] = rw1.z;
            B[(lcol + 3) * LDTB + lrow + 64] = rw1.w;
            __syncthreads();
            cur = nxt;
        }
    }

    // write logits tile (unpack f32x2 pairs; lo = even col)
#pragma unroll
    for (int i = 0; i < TM; ++i) {
        const int row = m0 + ty * TM + i;
        float* dst = g_logits + (size_t)row * NCOL + tx * TN;
        *(float4*)(dst)     = make_float4(lo_f32(acc2[i][0]), hi_f32(acc2[i][0]),
                                          lo_f32(acc2[i][1]), hi_f32(acc2[i][1]));
        *(float4*)(dst + 4) = make_float4(lo_f32(acc2[i][2]), hi_f32(acc2[i][2]),
                                          lo_f32(acc2[i][3]), hi_f32(acc2[i][3]));
    }
}

__device__ __forceinline__ float softplus_stable(float z)
{
    // log(1+exp(z)) = max(z,0) + log1p(exp(-|z|))
    return fmaxf(z, 0.f) + log1pf(expf(-fabsf(z)));
}

__global__ __launch_bounds__(256, 4)
void sg_gate(const float* __restrict__ noise, float* __restrict__ out)
{
    const int b = blockIdx.x * blockDim.x + threadIdx.x;
    if (b >= BROWS) return;

    const float4* lg = (const float4*)(g_logits + (size_t)b * NCOL);
    const float4* nz = (const float4*)(noise    + (size_t)b * EEXP);

    float v1 = -INFINITY, v2 = -INFINITY;
    int   i1 = -1, i2 = -1;

#pragma unroll
    for (int g = 0; g < 16; ++g) {
        float4 c = lg[g];        // clean logits e = 4g..4g+3
        float4 s = lg[16 + g];   // noisy logits
        float4 n = nz[g];        // noise
        float ev[4];
        ev[0] = c.x + n.x * softplus_stable(s.x);
        ev[1] = c.y + n.y * softplus_stable(s.y);
        ev[2] = c.z + n.z * softplus_stable(s.z);
        ev[3] = c.w + n.w * softplus_stable(s.w);
#pragma unroll
        for (int c4 = 0; c4 < 4; ++c4) {
            const float v = ev[c4];
            const int   e = 4 * g + c4;
            if (v > v1)      { v2 = v1; i2 = i1; v1 = v; i1 = e; }
            else if (v > v2) { v2 = v;  i2 = e; }
        }
    }

    // softmax over the two selected (v1 >= v2)
    const float ex = expf(v2 - v1);     // <= 1
    const float p1 = 1.f / (1.f + ex);
    const float p2 = 1.f - p1;

    float* o = out + (size_t)b * EEXP;
#pragma unroll
    for (int g = 0; g < 16; ++g) {
        const int e = 4 * g;
        float4 v;
        v.x = (e     == i1) ? p1 : ((e     == i2) ? p2 : 0.f);
        v.y = (e + 1 == i1) ? p1 : ((e + 1 == i2) ? p2 : 0.f);
        v.z = (e + 2 == i1) ? p1 : ((e + 2 == i2) ? p2 : 0.f);
        v.w = (e + 3 == i1) ? p1 : ((e + 3 == i2) ? p2 : 0.f);
        *(float4*)(o + e) = v;
    }
}

extern "C" void kernel_launch(void* const* d_in, const int* in_sizes, int n_in,
                              void* d_out, int out_size)
{
    const float* x     = (const float*)d_in[0];
    const float* gw    = (const float*)d_in[1];
    const float* nw    = (const float*)d_in[2];
    const float* noise = (const float*)d_in[3];
    // d_in[4] is k (=2), compile-time constant here

    cudaFuncSetAttribute(sg_gemm, cudaFuncAttributeMaxDynamicSharedMemorySize, SMEM_BYTES);
    sg_gemm<<<BROWS / BM, 256, SMEM_BYTES>>>(x, gw, nw);
    sg_gate<<<BROWS / 256, 256>>>(noise, (float*)d_out);
}

// round 5
// speedup vs baseline: 1.5755x; 1.5755x over previous
#include <cuda_runtime.h>
#include <math.h>
#include <stdint.h>

// Shapes (fixed by dataset)
#define BROWS 16384
#define DDIM  2048
#define EEXP  64
#define NCOL  128          // cols 0..63 gate logits, 64..127 noise logits

// Tiling
#define BM 128
#define BK 16              // K per chunk (2 x k8 mma steps)
#define NCHUNK (DDIM / BK) // 128
#define LDA 20             // smem row stride (floats): r*20 mod 32 -> conflict-free frag LDS
#define LDLOG 132          // epilogue logits row stride

// smem stage layout (floats): Ah | Al | Bh | Bl, each [128][LDA]
#define MAT_FLOATS  (128 * LDA)          // 2560
#define AH_OFF 0
#define AL_OFF (1 * MAT_FLOATS)
#define BH_OFF (2 * MAT_FLOATS)
#define BL_OFF (3 * MAT_FLOATS)
#define STAGE_FLOATS (4 * MAT_FLOATS)    // 10240
#define SMEM_FLOATS  (2 * STAGE_FLOATS)  // 20480  (also >= 128*LDLOG=16896 for epilogue)
#define SMEM_BYTES   (SMEM_FLOATS * 4)   // 81920

// m16n8k8 tf32 mma: D += A*B  (A row-major 16x8, B col-major 8x8)
#define MMA_TF32(c, a, b) \
    asm volatile("mma.sync.aligned.m16n8k8.row.col.f32.tf32.tf32.f32 " \
                 "{%0,%1,%2,%3}, {%4,%5,%6,%7}, {%8,%9}, {%0,%1,%2,%3};" \
                 : "+f"((c)[0]), "+f"((c)[1]), "+f"((c)[2]), "+f"((c)[3]) \
                 : "r"((a)[0]), "r"((a)[1]), "r"((a)[2]), "r"((a)[3]), \
                   "r"((b)[0]), "r"((b)[1]))

__device__ __forceinline__ uint32_t tf32_bits(float a) {
    uint32_t u;
    asm("cvt.rna.tf32.f32 %0, %1;" : "=r"(u) : "f"(a));
    return u;
}
// split float4 into tf32-hi (bit patterns) and tf32-lo (bit patterns)
__device__ __forceinline__ void split4(float4 v, uint4& h, uint4& l) {
    h.x = tf32_bits(v.x); h.y = tf32_bits(v.y); h.z = tf32_bits(v.z); h.w = tf32_bits(v.w);
    l.x = tf32_bits(v.x - __uint_as_float(h.x));
    l.y = tf32_bits(v.y - __uint_as_float(h.y));
    l.z = tf32_bits(v.z - __uint_as_float(h.z));
    l.w = tf32_bits(v.w - __uint_as_float(h.w));
}
__device__ __forceinline__ float softplus_stable(float z) {
    return fmaxf(z, 0.f) + log1pf(expf(-fabsf(z)));
}

__global__ __launch_bounds__(256, 1)
void sg_fused(const float* __restrict__ x,
              const float* __restrict__ gw,
              const float* __restrict__ nw,
              const float* __restrict__ noise,
              float* __restrict__ out)
{
    extern __shared__ float smem[];   // stages / epilogue logits

    const int tid  = threadIdx.x;
    const int wid  = tid >> 5;
    const int lane = tid & 31;
    const int m0   = blockIdx.x * BM;

    // warp tile: 32 rows x 64 cols.  warp_m in 0..3, warp_n in 0..1
    const int m_warp = (wid & 3) * 32;
    const int n_warp = (wid >> 2) * 64;

    // loader mapping (round-2 proven): each thread 2 float4 from A, 2 from W per chunk
    const int lrow  = tid >> 2;        // 0..63
    const int lcol4 = (tid & 3) * 4;   // 0,4,8,12

    const float* aptr0 = x  + (size_t)(m0 + lrow)      * DDIM + lcol4;
    const float* aptr1 = x  + (size_t)(m0 + lrow + 64) * DDIM + lcol4;
    const float* wptr0 = gw + (size_t)lrow * DDIM + lcol4;   // logits cols 0..63
    const float* wptr1 = nw + (size_t)lrow * DDIM + lcol4;   // logits cols 64..127

    float acc[2][8][4];
#pragma unroll
    for (int mt = 0; mt < 2; ++mt)
#pragma unroll
        for (int nt = 0; nt < 8; ++nt)
#pragma unroll
            for (int r = 0; r < 4; ++r) acc[mt][nt][r] = 0.f;

    // preload chunk 0
    float4 va0 = *(const float4*)(aptr0);
    float4 va1 = *(const float4*)(aptr1);
    float4 vb0 = *(const float4*)(wptr0);
    float4 vb1 = *(const float4*)(wptr1);

    // stage chunk 0 into buffer 0
    {
        float* S = smem;
        uint4 h, l;
        split4(va0, h, l);
        *(uint4*)&S[AH_OFF + lrow * LDA + lcol4] = h;
        *(uint4*)&S[AL_OFF + lrow * LDA + lcol4] = l;
        split4(va1, h, l);
        *(uint4*)&S[AH_OFF + (lrow + 64) * LDA + lcol4] = h;
        *(uint4*)&S[AL_OFF + (lrow + 64) * LDA + lcol4] = l;
        split4(vb0, h, l);
        *(uint4*)&S[BH_OFF + lrow * LDA + lcol4] = h;
        *(uint4*)&S[BL_OFF + lrow * LDA + lcol4] = l;
        split4(vb1, h, l);
        *(uint4*)&S[BH_OFF + (lrow + 64) * LDA + lcol4] = h;
        *(uint4*)&S[BL_OFF + (lrow + 64) * LDA + lcol4] = l;
    }
    __syncthreads();

    const int frow = lane >> 2;   // 0..7
    const int fcol = lane & 3;    // 0..3

    int cur = 0;
    for (int t = 0; t < NCHUNK; ++t) {
        const bool have_next = (t + 1 < NCHUNK);
        if (have_next) {
            const int off = (t + 1) * BK;
            va0 = *(const float4*)(aptr0 + off);
            va1 = *(const float4*)(aptr1 + off);
            vb0 = *(const float4*)(wptr0 + off);
            vb1 = *(const float4*)(wptr1 + off);
        }

        const float* S = smem + cur * STAGE_FLOATS;

#pragma unroll
        for (int k8 = 0; k8 < 2; ++k8) {
            const int kb = k8 * 8;
            uint32_t ah[2][4], al[2][4], bh[8][2], bl[8][2];
#pragma unroll
            for (int mt = 0; mt < 2; ++mt) {
                const int rb = m_warp + mt * 16 + frow;
                ah[mt][0] = __float_as_uint(S[AH_OFF + (rb)     * LDA + kb + fcol]);
                ah[mt][1] = __float_as_uint(S[AH_OFF + (rb + 8) * LDA + kb + fcol]);
                ah[mt][2] = __float_as_uint(S[AH_OFF + (rb)     * LDA + kb + fcol + 4]);
                ah[mt][3] = __float_as_uint(S[AH_OFF + (rb + 8) * LDA + kb + fcol + 4]);
                al[mt][0] = __float_as_uint(S[AL_OFF + (rb)     * LDA + kb + fcol]);
                al[mt][1] = __float_as_uint(S[AL_OFF + (rb + 8) * LDA + kb + fcol]);
                al[mt][2] = __float_as_uint(S[AL_OFF + (rb)     * LDA + kb + fcol + 4]);
                al[mt][3] = __float_as_uint(S[AL_OFF + (rb + 8) * LDA + kb + fcol + 4]);
            }
#pragma unroll
            for (int nt = 0; nt < 8; ++nt) {
                const int cb = n_warp + nt * 8 + frow;    // logits col (B row)
                bh[nt][0] = __float_as_uint(S[BH_OFF + cb * LDA + kb + fcol]);
                bh[nt][1] = __float_as_uint(S[BH_OFF + cb * LDA + kb + fcol + 4]);
                bl[nt][0] = __float_as_uint(S[BL_OFF + cb * LDA + kb + fcol]);
                bl[nt][1] = __float_as_uint(S[BL_OFF + cb * LDA + kb + fcol + 4]);
            }
            // 3 split passes: hh, hl, lh
#pragma unroll
            for (int mt = 0; mt < 2; ++mt)
#pragma unroll
                for (int nt = 0; nt < 8; ++nt)
                    MMA_TF32(acc[mt][nt], ah[mt], bh[nt]);
#pragma unroll
            for (int mt = 0; mt < 2; ++mt)
#pragma unroll
                for (int nt = 0; nt < 8; ++nt)
                    MMA_TF32(acc[mt][nt], ah[mt], bl[nt]);
#pragma unroll
            for (int mt = 0; mt < 2; ++mt)
#pragma unroll
                for (int nt = 0; nt < 8; ++nt)
                    MMA_TF32(acc[mt][nt], al[mt], bh[nt]);
        }

        if (have_next) {
            const int nxt = cur ^ 1;
            float* SN = smem + nxt * STAGE_FLOATS;
            uint4 h, l;
            split4(va0, h, l);
            *(uint4*)&SN[AH_OFF + lrow * LDA + lcol4] = h;
            *(uint4*)&SN[AL_OFF + lrow * LDA + lcol4] = l;
            split4(va1, h, l);
            *(uint4*)&SN[AH_OFF + (lrow + 64) * LDA + lcol4] = h;
            *(uint4*)&SN[AL_OFF + (lrow + 64) * LDA + lcol4] = l;
            split4(vb0, h, l);
            *(uint4*)&SN[BH_OFF + lrow * LDA + lcol4] = h;
            *(uint4*)&SN[BL_OFF + lrow * LDA + lcol4] = l;
            split4(vb1, h, l);
            *(uint4*)&SN[BH_OFF + (lrow + 64) * LDA + lcol4] = h;
            *(uint4*)&SN[BL_OFF + (lrow + 64) * LDA + lcol4] = l;
            __syncthreads();
            cur = nxt;
        }
    }

    // ===== epilogue: exchange logits through smem, fused gate =====
    __syncthreads();   // everyone done reading stage buffers
#pragma unroll
    for (int mt = 0; mt < 2; ++mt) {
        const int r0 = m_warp + mt * 16 + frow;
#pragma unroll
        for (int nt = 0; nt < 8; ++nt) {
            const int col = n_warp + nt * 8 + fcol * 2;
            *(float2*)&smem[(r0)     * LDLOG + col] = make_float2(acc[mt][nt][0], acc[mt][nt][1]);
            *(float2*)&smem[(r0 + 8) * LDLOG + col] = make_float2(acc[mt][nt][2], acc[mt][nt][3]);
        }
    }
    __syncthreads();

    if (tid < BM) {
        const int   row  = tid;
        const int   rowg = m0 + row;
        const float* lg  = smem + row * LDLOG;                       // [0..63] clean, [64..127] noisy
        const float4* nz = (const float4*)(noise + (size_t)rowg * EEXP);

        float v1 = -INFINITY, v2 = -INFINITY;
        int   i1 = -1, i2 = -1;
#pragma unroll
        for (int g = 0; g < 16; ++g) {
            const float4 c = *(const float4*)(lg + 4 * g);
            const float4 s = *(const float4*)(lg + 64 + 4 * g);
            const float4 n = nz[g];
            float ev[4];
            ev[0] = c.x + n.x * softplus_stable(s.x);
            ev[1] = c.y + n.y * softplus_stable(s.y);
            ev[2] = c.z + n.z * softplus_stable(s.z);
            ev[3] = c.w + n.w * softplus_stable(s.w);
#pragma unroll
            for (int c4 = 0; c4 < 4; ++c4) {
                const float v = ev[c4];
                const int   e = 4 * g + c4;
                if (v > v1)      { v2 = v1; i2 = i1; v1 = v; i1 = e; }
                else if (v > v2) { v2 = v;  i2 = e; }
            }
        }
        const float ex = expf(v2 - v1);
        const float p1 = 1.f / (1.f + ex);
        const float p2 = 1.f - p1;

        float* o = out + (size_t)rowg * EEXP;
#pragma unroll
        for (int g = 0; g < 16; ++g) {
            const int e = 4 * g;
            float4 v;
            v.x = (e     == i1) ? p1 : ((e     == i2) ? p2 : 0.f);
            v.y = (e + 1 == i1) ? p1 : ((e + 1 == i2) ? p2 : 0.f);
            v.z = (e + 2 == i1) ? p1 : ((e + 2 == i2) ? p2 : 0.f);
            v.w = (e + 3 == i1) ? p1 : ((e + 3 == i2) ? p2 : 0.f);
            *(float4*)(o + e) = v;
        }
    }
}

extern "C" void kernel_launch(void* const* d_in, const int* in_sizes, int n_in,
                              void* d_out, int out_size)
{
    const float* x     = (const float*)d_in[0];
    const float* gw    = (const float*)d_in[1];
    const float* nw    = (const float*)d_in[2];
    const float* noise = (const float*)d_in[3];
    // d_in[4] is k (=2), compile-time constant

    cudaFuncSetAttribute(sg_fused, cudaFuncAttributeMaxDynamicSharedMemorySize, SMEM_BYTES);
    sg_fused<<<BROWS / BM, 256, SMEM_BYTES>>>(x, gw, nw, noise, (float*)d_out);
}